// round 16
// baseline (speedup 1.0000x reference)
#include <cuda_runtime.h>
#include <cuda_fp16.h>
#include <stdint.h>

#define NN 100000
#define DD 512
#define SS 4

// Static device scratch (no allocs allowed)
__device__ uint16_t g_Wh[DD * DD];             // W rounded to fp16
__device__ float    g_P[2 * 5 * NN];           // partial dots per N-half

// ---------------------------------------------------------------------------
// helpers
// ---------------------------------------------------------------------------
__device__ __forceinline__ uint32_t smem_u32(const void* p) {
    uint32_t a;
    asm("{ .reg .u64 t; cvta.to.shared.u64 t, %1; cvt.u32.u64 %0, t; }"
        : "=r"(a) : "l"(p));
    return a;
}
__device__ __forceinline__ uint32_t pack_f16(float x, float y) {
    uint32_t r;
    asm("cvt.rn.f16x2.f32 %0, %1, %2;" : "=r"(r) : "f"(y), "f"(x));
    return r;
}
__device__ __forceinline__ void mma16816(float c[4], const uint32_t a[4],
                                         uint32_t b0, uint32_t b1) {
    asm volatile(
        "mma.sync.aligned.m16n8k16.row.col.f32.f16.f16.f32 "
        "{%0,%1,%2,%3}, {%4,%5,%6,%7}, {%8,%9}, {%0,%1,%2,%3};"
        : "+f"(c[0]), "+f"(c[1]), "+f"(c[2]), "+f"(c[3])
        : "r"(a[0]), "r"(a[1]), "r"(a[2]), "r"(a[3]), "r"(b0), "r"(b1));
}
__device__ __forceinline__ void ldm_x4(uint32_t addr, uint32_t& r0, uint32_t& r1,
                                       uint32_t& r2, uint32_t& r3) {
    asm volatile("ldmatrix.sync.aligned.m8n8.x4.shared.b16 {%0,%1,%2,%3}, [%4];"
                 : "=r"(r0), "=r"(r1), "=r"(r2), "=r"(r3) : "r"(addr));
}
__device__ __forceinline__ void cp16(uint32_t dst, const void* src) {
    asm volatile("cp.async.cg.shared.global [%0], [%1], 16;"
                 :: "r"(dst), "l"(src));
}
__device__ __forceinline__ void cp_commit() {
    asm volatile("cp.async.commit_group;" ::: "memory");
}
__device__ __forceinline__ void cp_wait0() {
    asm volatile("cp.async.wait_group 0;" ::: "memory");
}
__device__ __forceinline__ void cp_wait1() {
    asm volatile("cp.async.wait_group 1;" ::: "memory");
}

// ---------------------------------------------------------------------------
// Kernel 0: round W [512x512] fp32 -> fp16 (once per launch, ~4us)
// ---------------------------------------------------------------------------
__global__ __launch_bounds__(256) void round_w(const float* __restrict__ W) {
    const int i = blockIdx.x * 256 + threadIdx.x;   // over 131072 float2
    const float2 f = ((const float2*)W)[i];
    ((uint32_t*)g_Wh)[i] = pack_f16(f.x, f.y);
}

// ---------------------------------------------------------------------------
// Fused GEMM + partial dots. CTA: 64(M) x 256(N-half), 256 threads (8 warps,
// warp tile 64x32). fp16 single-pass, fp32 acc. BK=64 (8 chunks, 8 barriers),
// B triple-buffered via cp.async, A double-buffered via LDG+cvt+STS.
// Smem rows are exactly 128B with XOR-16B-segment swizzle (conflict-free,
// no padding) -> 3-stage fits 2 CTAs/SM: 114688 B/CTA.
// ---------------------------------------------------------------------------
constexpr int BM = 64, BN = 256, BK = 64;
constexpr int NCH = DD / BK;           // 8 chunks
constexpr int RS = 128;                // row stride bytes (no pad, swizzled)
constexpr int A_0 = 0;                           // 2 bufs x 64*128  = 16384
constexpr int B_0 = 2 * BM * RS;                 // 16384; 3 bufs x 256*128
constexpr int MAIN_BYTES = B_0 + 3 * BN * RS;    // 114688
constexpr int VST = 260;                         // V staging stride (words)
constexpr int SMEM_BYTES = MAIN_BYTES;           // > V staging (66560)
#define A_BUF(b) (A_0 + (b) * BM * RS)
#define B_BUF(b) (B_0 + (b) * BN * RS)

__global__ __launch_bounds__(256, 2) void gemm_fused(const float* __restrict__ A,
                                                     const float* __restrict__ hpl,
                                                     const int* __restrict__ samp) {
    extern __shared__ char smem[];
    const uint32_t sb = smem_u32(smem);
    const int tid = threadIdx.x;
    const int wid = tid >> 5;          // 0..7
    const int lane = tid & 31;
    const int t = lane & 3;
    const int half = blockIdx.x;       // which 256-col half of W
    const int bn = half * BN;
    const int bm = blockIdx.y * BM;

    float acc[4][4][4];
#pragma unroll
    for (int i = 0; i < 4; i++)
#pragma unroll
        for (int j = 0; j < 4; j++)
#pragma unroll
            for (int q = 0; q < 4; q++) acc[i][j][q] = 0.f;

    // A tile: 64 rows x 64 fp32 cols; thread -> (row = tid>>5 + it*8, float2 col)
    const int a_row0 = tid >> 5;       // 0..7
    const int a_c2 = tid & 31;         // float2 col 0..31
    const int a_sw = ((a_c2 >> 2) ^ a_row0) << 4;   // row&7 == a_row0 for all its
    const int a_sb = (a_c2 & 3) << 2;
    // B tile: 256 rows x 8 16B-segs; thread -> (row = tid>>3 + it*32, seg)
    const int b_row0 = tid >> 3;       // 0..31
    const int b_seg = tid & 7;
    const int b_swseg = (b_seg ^ (b_row0 & 7)) << 4;  // row&7 == b_row0&7

    // ldmatrix lane components (row&7 == lr for both A and B fragments)
    const int grp = lane >> 3;
    const int lr = lane & 7;
    const int a_lrow = (grp & 1) * 8 + lr;
    const int a_sg = grp >> 1;         // A k-seg offset (0/1)
    const int b_sg = grp & 1;          // B k-seg offset (0/1)
    const int b_jadd = (grp >> 1) * 8 + lr;

    float2 areg[8];

    auto loadA = [&](int kc) {
#pragma unroll
        for (int it = 0; it < 8; it++) {
            const int row = a_row0 + it * 8;
            const int gr = bm + row;
            areg[it] = make_float2(0.f, 0.f);
            if (gr < NN)
                areg[it] = *(const float2*)&A[(size_t)gr * DD + kc * BK + a_c2 * 2];
        }
    };
    auto storeA = [&](int buf) {
#pragma unroll
        for (int it = 0; it < 8; it++) {
            const int row = a_row0 + it * 8;
            *(uint32_t*)(smem + A_BUF(buf) + row * RS + a_sw + a_sb) =
                pack_f16(areg[it].x, areg[it].y);
        }
    };
    auto issueB = [&](int kc, int buf) {
#pragma unroll
        for (int it = 0; it < 8; it++) {
            const int row = b_row0 + it * 32;
            const size_t gsrc = (size_t)(bn + row) * DD + kc * BK + b_seg * 8;
            cp16(sb + B_BUF(buf) + row * RS + b_swseg, g_Wh + gsrc);
        }
        cp_commit();
    };

    // prologue: B chunks 0,1 in flight; A chunk 0 staged
    loadA(0);
    issueB(0, 0);
    issueB(1, 1);
    storeA(0);
    cp_wait1();            // B0 landed
    __syncthreads();

    for (int kc = 0; kc < NCH; kc++) {
        const int curA = kc & 1;
        const int curB = kc % 3;
        if (kc + 2 < NCH) issueB(kc + 2, (kc + 2) % 3);
        if (kc + 1 < NCH) loadA(kc + 1);

#pragma unroll
        for (int s = 0; s < 4; s++) {          // 4 k-steps of 16 per chunk
            uint32_t ah[4][4];
#pragma unroll
            for (int i = 0; i < 4; i++) {
                const int row_a = i * 16 + a_lrow;
                const uint32_t aoff =
                    row_a * RS + ((((2 * s + a_sg)) ^ lr) << 4);
                ldm_x4(sb + A_BUF(curA) + aoff, ah[i][0], ah[i][1], ah[i][2], ah[i][3]);
            }
            uint32_t bh[4][2];
#pragma unroll
            for (int jj = 0; jj < 2; jj++) {
                const int row_b = wid * 32 + jj * 16 + b_jadd;
                const uint32_t boff =
                    row_b * RS + ((((2 * s + b_sg)) ^ lr) << 4);
                ldm_x4(sb + B_BUF(curB) + boff, bh[jj * 2][0], bh[jj * 2][1],
                       bh[jj * 2 + 1][0], bh[jj * 2 + 1][1]);
            }
#pragma unroll
            for (int j = 0; j < 4; j++)
#pragma unroll
                for (int i = 0; i < 4; i++)
                    mma16816(acc[i][j], ah[i], bh[j][0], bh[j][1]);
        }

        if (kc + 1 < NCH) {
            storeA(curA ^ 1);
            if (kc + 2 < NCH) cp_wait1();   // B(kc+1) is oldest outstanding
            else cp_wait0();
            __syncthreads();
        }
    }

    __syncthreads();

    // ---- stage V half-tile [64 x 256] into smem (stride 260) ----
    const int g8 = lane >> 2;
    float* sV = (float*)smem;
#pragma unroll
    for (int i = 0; i < 4; i++) {
#pragma unroll
        for (int j = 0; j < 4; j++) {
            const int col = wid * 32 + j * 8 + t * 2;
            const int r0 = i * 16 + g8;
            const int r1 = r0 + 8;
            sV[r0 * VST + col] = acc[i][j][0];
            sV[r0 * VST + col + 1] = acc[i][j][1];
            sV[r1 * VST + col] = acc[i][j][2];
            sV[r1 * VST + col + 1] = acc[i][j][3];
        }
    }
    __syncthreads();

    // ---- partial dots over this 256-col half: warp wid -> rows wid*8..+7 ----
#pragma unroll
    for (int rr = 0; rr < 8; rr++) {
        const int row = wid * 8 + rr;
        const int n = bm + row;
        if (n >= NN) break;

        const float4* __restrict__ v = (const float4*)(sV + row * VST);
        const float4* __restrict__ p = (const float4*)(hpl + (size_t)n * DD + bn);
        const float4* __restrict__ g0 = (const float4*)(A + (size_t)samp[0 * NN + n] * DD + bn);
        const float4* __restrict__ g1 = (const float4*)(A + (size_t)samp[1 * NN + n] * DD + bn);
        const float4* __restrict__ g2 = (const float4*)(A + (size_t)samp[2 * NN + n] * DD + bn);
        const float4* __restrict__ g3 = (const float4*)(A + (size_t)samp[3 * NN + n] * DD + bn);

        float a0 = 0.f, a1 = 0.f, a2 = 0.f, a3 = 0.f, a4 = 0.f;
#pragma unroll
        for (int c = lane; c < BN / 4; c += 32) {
            const float4 vv = v[c];
            float4 x;
            x = p[c];  a0 += vv.x * x.x + vv.y * x.y + vv.z * x.z + vv.w * x.w;
            x = g0[c]; a1 += vv.x * x.x + vv.y * x.y + vv.z * x.z + vv.w * x.w;
            x = g1[c]; a2 += vv.x * x.x + vv.y * x.y + vv.z * x.z + vv.w * x.w;
            x = g2[c]; a3 += vv.x * x.x + vv.y * x.y + vv.z * x.z + vv.w * x.w;
            x = g3[c]; a4 += vv.x * x.x + vv.y * x.y + vv.z * x.z + vv.w * x.w;
        }
#pragma unroll
        for (int off = 16; off > 0; off >>= 1) {
            a0 += __shfl_xor_sync(0xFFFFFFFFu, a0, off);
            a1 += __shfl_xor_sync(0xFFFFFFFFu, a1, off);
            a2 += __shfl_xor_sync(0xFFFFFFFFu, a2, off);
            a3 += __shfl_xor_sync(0xFFFFFFFFu, a3, off);
            a4 += __shfl_xor_sync(0xFFFFFFFFu, a4, off);
        }
        if (lane == 0) {
            float* P = g_P + (size_t)half * 5 * NN;
            P[0 * NN + n] = a0;
            P[1 * NN + n] = a1;
            P[2 * NN + n] = a2;
            P[3 * NN + n] = a3;
            P[4 * NN + n] = a4;
        }
    }
}

// ---------------------------------------------------------------------------
// Combine: out = P[half0] + P[half1] + b, scattered to 9 positions per n.
// ---------------------------------------------------------------------------
__global__ __launch_bounds__(256) void combine(const float* __restrict__ bptr,
                                               float* __restrict__ out) {
    const int n = blockIdx.x * 256 + threadIdx.x;
    if (n >= NN) return;
    const float b = bptr[0];
    const float s0 = g_P[0 * NN + n] + g_P[(5 + 0) * NN + n] + b;
    const float s1 = g_P[1 * NN + n] + g_P[(5 + 1) * NN + n] + b;
    const float s2 = g_P[2 * NN + n] + g_P[(5 + 2) * NN + n] + b;
    const float s3 = g_P[3 * NN + n] + g_P[(5 + 3) * NN + n] + b;
    const float s4 = g_P[4 * NN + n] + g_P[(5 + 4) * NN + n] + b;
    out[n] = s0;
    out[NN + 0 * NN + n] = s1;  out[NN + (SS + 0) * NN + n] = s1;
    out[NN + 1 * NN + n] = s2;  out[NN + (SS + 1) * NN + n] = s2;
    out[NN + 2 * NN + n] = s3;  out[NN + (SS + 2) * NN + n] = s3;
    out[NN + 3 * NN + n] = s4;  out[NN + (SS + 3) * NN + n] = s4;
}

extern "C" void kernel_launch(void* const* d_in, const int* in_sizes, int n_in,
                              void* d_out, int out_size) {
    const float* h_c  = (const float*)d_in[0];
    const float* h_pl = (const float*)d_in[1];
    const int*   samp = (const int*)d_in[2];
    const float* W    = (const float*)d_in[3];
    const float* b    = (const float*)d_in[4];
    float* out = (float*)d_out;

    round_w<<<512, 256>>>(W);

    static int smem_set = 0;
    if (!smem_set) {
        cudaFuncSetAttribute(gemm_fused, cudaFuncAttributeMaxDynamicSharedMemorySize,
                             SMEM_BYTES);
        smem_set = 1;
    }
    dim3 grid(2, (NN + BM - 1) / BM);   // (2, 1563)
    gemm_fused<<<grid, 256, SMEM_BYTES>>>(h_c, h_pl, samp);

    combine<<<(NN + 255) / 256, 256>>>(b, out);
}

// round 17
// speedup vs baseline: 1.1745x; 1.1745x over previous
#include <cuda_runtime.h>
#include <cuda_fp16.h>
#include <stdint.h>

#define NN 100000
#define DD 512
#define SS 4

// Static device scratch (no allocs allowed)
__device__ uint16_t g_Wh[DD * DD];             // W rounded to fp16
__device__ float    g_P[2 * 5 * NN];           // partial dots per N-half

// ---------------------------------------------------------------------------
// helpers
// ---------------------------------------------------------------------------
__device__ __forceinline__ uint32_t smem_u32(const void* p) {
    uint32_t a;
    asm("{ .reg .u64 t; cvta.to.shared.u64 t, %1; cvt.u32.u64 %0, t; }"
        : "=r"(a) : "l"(p));
    return a;
}
__device__ __forceinline__ uint32_t pack_f16(float x, float y) {
    uint32_t r;
    asm("cvt.rn.f16x2.f32 %0, %1, %2;" : "=r"(r) : "f"(y), "f"(x));
    return r;
}
__device__ __forceinline__ void mma16816(float c[4], const uint32_t a[4],
                                         uint32_t b0, uint32_t b1) {
    asm volatile(
        "mma.sync.aligned.m16n8k16.row.col.f32.f16.f16.f32 "
        "{%0,%1,%2,%3}, {%4,%5,%6,%7}, {%8,%9}, {%0,%1,%2,%3};"
        : "+f"(c[0]), "+f"(c[1]), "+f"(c[2]), "+f"(c[3])
        : "r"(a[0]), "r"(a[1]), "r"(a[2]), "r"(a[3]), "r"(b0), "r"(b1));
}
__device__ __forceinline__ void ldm_x4(uint32_t addr, uint32_t& r0, uint32_t& r1,
                                       uint32_t& r2, uint32_t& r3) {
    asm volatile("ldmatrix.sync.aligned.m8n8.x4.shared.b16 {%0,%1,%2,%3}, [%4];"
                 : "=r"(r0), "=r"(r1), "=r"(r2), "=r"(r3) : "r"(addr));
}
__device__ __forceinline__ void cp16(uint32_t dst, const void* src) {
    asm volatile("cp.async.cg.shared.global [%0], [%1], 16;"
                 :: "r"(dst), "l"(src));
}
__device__ __forceinline__ void cp_commit() {
    asm volatile("cp.async.commit_group;" ::: "memory");
}
__device__ __forceinline__ void cp_wait_all() {
    asm volatile("cp.async.wait_group 0;" ::: "memory");
}

// ---------------------------------------------------------------------------
// Kernel 0: round W [512x512] fp32 -> fp16 (once per launch, ~4us)
// ---------------------------------------------------------------------------
__global__ __launch_bounds__(256) void round_w(const float* __restrict__ W) {
    const int i = blockIdx.x * 256 + threadIdx.x;   // over 131072 float2
    const float2 f = ((const float2*)W)[i];
    ((uint32_t*)g_Wh)[i] = pack_f16(f.x, f.y);
}

// ---------------------------------------------------------------------------
// Fused GEMM + partial dots (R14 structure: BK=64, 2-stage, 8 barriers).
// CTA: 64(M) x 256(N-half), 256 threads (8 warps, warp tile 64x32).
// fp16 single-pass, fp32 accumulate. A via float4 LDG + cvt + STS,
// B via cp.async from pre-rounded g_Wh.
// ---------------------------------------------------------------------------
constexpr int BM = 64, BN = 256, BK = 64;
constexpr int NCH = DD / BK;           // 8 chunks
constexpr int RS = 144;                // row stride bytes (128B data + 16B pad)
constexpr int A_0 = 0;                           // 2 bufs x 64*144  = 18432
constexpr int B_0 = 2 * BM * RS;                 // 18432; 2 bufs x 256*144
constexpr int MAIN_BYTES = B_0 + 2 * BN * RS;    // 92160
constexpr int VST = 260;                         // V staging stride (words)
constexpr int SMEM_BYTES = MAIN_BYTES;           // > V staging (66560)
#define A_BUF(b) (A_0 + (b) * BM * RS)
#define B_BUF(b) (B_0 + (b) * BN * RS)

__global__ __launch_bounds__(256, 2) void gemm_fused(const float* __restrict__ A,
                                                     const float* __restrict__ hpl,
                                                     const int* __restrict__ samp) {
    extern __shared__ char smem[];
    const uint32_t sb = smem_u32(smem);
    const int tid = threadIdx.x;
    const int wid = tid >> 5;          // 0..7
    const int lane = tid & 31;
    const int t = lane & 3;
    const int half = blockIdx.x;       // which 256-col half of W
    const int bn = half * BN;
    const int bm = blockIdx.y * BM;

    float acc[4][4][4];
#pragma unroll
    for (int i = 0; i < 4; i++)
#pragma unroll
        for (int j = 0; j < 4; j++)
#pragma unroll
            for (int q = 0; q < 4; q++) acc[i][j][q] = 0.f;

    // A tile: 64 rows x 64 fp32 cols = 1024 float4; 4 per thread
    const int a_row0 = tid >> 4;       // item = tid + it*256; row = item>>4
    const int a_c4 = tid & 15;         // float4 col 0..15
    // B tile: 256 rows x 128B; 2048 x 16B chunks; 8 per thread
    const int b_row0 = tid >> 3;
    const int b_seg = tid & 7;

    const int grp = lane >> 3;
    const int lr = lane & 7;
    const int a_lrow = (grp & 1) * 8 + lr;
    const int a_kadd = (grp >> 1) * 16;
    const int b_kadd = (grp & 1) * 16;
    const int b_jadd = (grp >> 1) * 8 + lr;

    float4 areg[4];

    auto loadA = [&](int kc) {
#pragma unroll
        for (int it = 0; it < 4; it++) {
            const int row = a_row0 + it * 16;
            const int gr = bm + row;
            areg[it] = make_float4(0.f, 0.f, 0.f, 0.f);
            if (gr < NN)
                areg[it] = *(const float4*)&A[(size_t)gr * DD + kc * BK + a_c4 * 4];
        }
    };
    auto storeA = [&](int buf) {
#pragma unroll
        for (int it = 0; it < 4; it++) {
            const int row = a_row0 + it * 16;
            uint2 o;
            o.x = pack_f16(areg[it].x, areg[it].y);
            o.y = pack_f16(areg[it].z, areg[it].w);
            *(uint2*)(smem + A_BUF(buf) + row * RS + a_c4 * 8) = o;
        }
    };
    auto issueB = [&](int kc, int buf) {
#pragma unroll
        for (int it = 0; it < 8; it++) {
            const int item = tid + it * 256;
            const int row = item >> 3;
            const int seg = item & 7;
            const size_t gsrc = (size_t)(bn + row) * DD + kc * BK + seg * 8;
            cp16(sb + B_BUF(buf) + row * RS + seg * 16, g_Wh + gsrc);
        }
        cp_commit();
    };

    loadA(0);
    issueB(0, 0);
    storeA(0);
    cp_wait_all();
    __syncthreads();

    for (int kc = 0; kc < NCH; kc++) {
        const int cur = kc & 1;
        const int nxt = cur ^ 1;
        if (kc + 1 < NCH) {
            loadA(kc + 1);
            issueB(kc + 1, nxt);
        }

#pragma unroll
        for (int s = 0; s < 4; s++) {          // 4 k-steps of 16 per chunk
            const int koff = s * 32;
            uint32_t ah[4][4];
#pragma unroll
            for (int i = 0; i < 4; i++) {
                const uint32_t aoff = (i * 16 + a_lrow) * RS + koff + a_kadd;
                ldm_x4(sb + A_BUF(cur) + aoff, ah[i][0], ah[i][1], ah[i][2], ah[i][3]);
            }
            uint32_t bh[4][2];
#pragma unroll
            for (int jj = 0; jj < 2; jj++) {
                const uint32_t boff =
                    (wid * 32 + jj * 16 + b_jadd) * RS + koff + b_kadd;
                ldm_x4(sb + B_BUF(cur) + boff, bh[jj * 2][0], bh[jj * 2][1],
                       bh[jj * 2 + 1][0], bh[jj * 2 + 1][1]);
            }
#pragma unroll
            for (int j = 0; j < 4; j++)
#pragma unroll
                for (int i = 0; i < 4; i++)
                    mma16816(acc[i][j], ah[i], bh[j][0], bh[j][1]);
        }

        if (kc + 1 < NCH) storeA(nxt);
        cp_wait_all();
        __syncthreads();
    }

    // ---- stage V half-tile [64 x 256] into smem (stride 260) ----
    const int g8 = lane >> 2;
    float* sV = (float*)smem;
#pragma unroll
    for (int i = 0; i < 4; i++) {
#pragma unroll
        for (int j = 0; j < 4; j++) {
            const int col = wid * 32 + j * 8 + t * 2;
            const int r0 = i * 16 + g8;
            const int r1 = r0 + 8;
            sV[r0 * VST + col] = acc[i][j][0];
            sV[r0 * VST + col + 1] = acc[i][j][1];
            sV[r1 * VST + col] = acc[i][j][2];
            sV[r1 * VST + col + 1] = acc[i][j][3];
        }
    }
    __syncthreads();

    // ---- partial dots over this 256-col half: warp wid -> rows wid*8..+7 ----
#pragma unroll
    for (int rr = 0; rr < 8; rr++) {
        const int row = wid * 8 + rr;
        const int n = bm + row;
        if (n >= NN) break;

        const float4* __restrict__ v = (const float4*)(sV + row * VST);
        const float4* __restrict__ p = (const float4*)(hpl + (size_t)n * DD + bn);
        const float4* __restrict__ g0 = (const float4*)(A + (size_t)samp[0 * NN + n] * DD + bn);
        const float4* __restrict__ g1 = (const float4*)(A + (size_t)samp[1 * NN + n] * DD + bn);
        const float4* __restrict__ g2 = (const float4*)(A + (size_t)samp[2 * NN + n] * DD + bn);
        const float4* __restrict__ g3 = (const float4*)(A + (size_t)samp[3 * NN + n] * DD + bn);

        float a0 = 0.f, a1 = 0.f, a2 = 0.f, a3 = 0.f, a4 = 0.f;
#pragma unroll
        for (int c = lane; c < BN / 4; c += 32) {
            const float4 vv = v[c];
            float4 x;
            x = p[c];  a0 += vv.x * x.x + vv.y * x.y + vv.z * x.z + vv.w * x.w;
            x = g0[c]; a1 += vv.x * x.x + vv.y * x.y + vv.z * x.z + vv.w * x.w;
            x = g1[c]; a2 += vv.x * x.x + vv.y * x.y + vv.z * x.z + vv.w * x.w;
            x = g2[c]; a3 += vv.x * x.x + vv.y * x.y + vv.z * x.z + vv.w * x.w;
            x = g3[c]; a4 += vv.x * x.x + vv.y * x.y + vv.z * x.z + vv.w * x.w;
        }
#pragma unroll
        for (int off = 16; off > 0; off >>= 1) {
            a0 += __shfl_xor_sync(0xFFFFFFFFu, a0, off);
            a1 += __shfl_xor_sync(0xFFFFFFFFu, a1, off);
            a2 += __shfl_xor_sync(0xFFFFFFFFu, a2, off);
            a3 += __shfl_xor_sync(0xFFFFFFFFu, a3, off);
            a4 += __shfl_xor_sync(0xFFFFFFFFu, a4, off);
        }
        if (lane == 0) {
            float* P = g_P + (size_t)half * 5 * NN;
            P[0 * NN + n] = a0;
            P[1 * NN + n] = a1;
            P[2 * NN + n] = a2;
            P[3 * NN + n] = a3;
            P[4 * NN + n] = a4;
        }
    }
}

// ---------------------------------------------------------------------------
// Combine: out = P[half0] + P[half1] + b, scattered to 9 positions per n.
// ---------------------------------------------------------------------------
__global__ __launch_bounds__(256) void combine(const float* __restrict__ bptr,
                                               float* __restrict__ out) {
    const int n = blockIdx.x * 256 + threadIdx.x;
    if (n >= NN) return;
    const float b = bptr[0];
    const float s0 = g_P[0 * NN + n] + g_P[(5 + 0) * NN + n] + b;
    const float s1 = g_P[1 * NN + n] + g_P[(5 + 1) * NN + n] + b;
    const float s2 = g_P[2 * NN + n] + g_P[(5 + 2) * NN + n] + b;
    const float s3 = g_P[3 * NN + n] + g_P[(5 + 3) * NN + n] + b;
    const float s4 = g_P[4 * NN + n] + g_P[(5 + 4) * NN + n] + b;
    out[n] = s0;
    out[NN + 0 * NN + n] = s1;  out[NN + (SS + 0) * NN + n] = s1;
    out[NN + 1 * NN + n] = s2;  out[NN + (SS + 1) * NN + n] = s2;
    out[NN + 2 * NN + n] = s3;  out[NN + (SS + 2) * NN + n] = s3;
    out[NN + 3 * NN + n] = s4;  out[NN + (SS + 3) * NN + n] = s4;
}

extern "C" void kernel_launch(void* const* d_in, const int* in_sizes, int n_in,
                              void* d_out, int out_size) {
    const float* h_c  = (const float*)d_in[0];
    const float* h_pl = (const float*)d_in[1];
    const int*   samp = (const int*)d_in[2];
    const float* W    = (const float*)d_in[3];
    const float* b    = (const float*)d_in[4];
    float* out = (float*)d_out;

    round_w<<<512, 256>>>(W);

    static int smem_set = 0;
    if (!smem_set) {
        cudaFuncSetAttribute(gemm_fused, cudaFuncAttributeMaxDynamicSharedMemorySize,
                             SMEM_BYTES);
        smem_set = 1;
    }
    dim3 grid(2, (NN + BM - 1) / BM);   // (2, 1563)
    gemm_fused<<<grid, 256, SMEM_BYTES>>>(h_c, h_pl, samp);

    combine<<<(NN + 255) / 256, 256>>>(b, out);
}